// round 17
// baseline (speedup 1.0000x reference)
#include <cuda_runtime.h>
#include <cuda_bf16.h>
#include <cuda_fp8.h>
#include <cstdint>
#include <math.h>

#define NB 16
#define NC 128
#define NH 64
#define NW 64
#define NS 17            // 2*8+1 shifts per axis
#define NPOS 289         // 17*17
#define PLANE (NH*NW)    // 4096
#define CHW (NC*PLANE)   // 524288

#define SW 84            // padded sat plane byte stride (mult of 4; 21 words, odd)
#define SROWS 84         // 64 + 16 shift + spill rows (di<=18)
#define SPN (SROWS*SW)   // 7056 bytes per shift copy (1764 words; %32=4)
#define GSB 272          // grd smem n-stride bytes (16B-aligned; 68 words %32=4 -> ldsm conflict-free)
#define BUFB (16*GSB)    // one grd band buffer (16 n x 256 fp8) = 4352 B
#define NSTAGE 3         // cp.async ring depth
#define CSPL 37          // k-split: 16 m x 37 = 592 blocks = exactly 4/SM on 148 SMs
#define NBT (NC*16)      // 2048 total 4-row bands per m
#define NTILE 10         // p-tiles per warp (4 warps x 10 x 8 = 320)

// Persistent device scratch (no allocations allowed).
__device__ float d_dot[NB*NB*NPOS];            // raw correlation sums (atomic, zeroed in k_prep)
__device__ float d_part[NB*NPOS];              // raw window energy sums
__device__ float d_gsqp[NB][8];                // ||grd_n||^2 partials
__device__ float d_epart[NB*16*PLANE];         // per-(m, 8-ch group) energy partials
__device__ float d_dist[NB*NB];                // dist matrix
__device__ unsigned char d_sat8[NB*CHW];       // fp8 e4m3 copy of sat
__device__ unsigned char d_grd8[NB*CHW];       // fp8 e4m3 copy of grd

__device__ __forceinline__ unsigned char f2e4m3(float v) {
    return (unsigned char)__nv_cvt_float_to_fp8(v, __NV_SATFINITE, __NV_E4M3);
}

// ---------------------------------------------------------------------------
// Fused prologue. grid (NB, 24), 1024 threads. 384 balanced blocks.
//  y in [0,16) : sat (m=x, cgroup=y of 8 channels): fp32->fp8 convert +
//                per-pixel 8-channel energy partial -> d_epart.
//  y in [16,24): grd (n=x, cs=y-16 of 16 channels): fp32->fp8 convert +
//                gsq partial + distributed d_dot zeroing.
__global__ __launch_bounds__(1024)
void k_prep(const float* __restrict__ satf, const float* __restrict__ grdf) {
    int t = threadIdx.x;
    if (blockIdx.y < 16) {
        int m = blockIdx.x, cg = blockIdx.y;
        const float4* src = (const float4*)(satf + (size_t)m * CHW) + cg * 8 * 1024;
        unsigned* dst = (unsigned*)(d_sat8 + (size_t)m * CHW) + cg * 8 * 1024;
        float a0 = 0.f, a1 = 0.f, a2 = 0.f, a3 = 0.f;
#pragma unroll
        for (int c = 0; c < 8; c++) {
            float4 v = src[t + c * 1024];
            a0 = fmaf(v.x, v.x, a0); a1 = fmaf(v.y, v.y, a1);
            a2 = fmaf(v.z, v.z, a2); a3 = fmaf(v.w, v.w, a3);
            unsigned o = (unsigned)f2e4m3(v.x) | ((unsigned)f2e4m3(v.y) << 8)
                       | ((unsigned)f2e4m3(v.z) << 16) | ((unsigned)f2e4m3(v.w) << 24);
            dst[t + c * 1024] = o;
        }
        float4 e; e.x = a0; e.y = a1; e.z = a2; e.w = a3;
        ((float4*)d_epart)[(m * 16 + cg) * 1024 + t] = e;
    } else {
        int n = blockIdx.x, cs = blockIdx.y - 16;  // cs in [0,8)
        int gid = (n * 8 + cs) * 1024 + t;
        if (gid < NB * NB * NPOS) d_dot[gid] = 0.f;

        size_t base = (size_t)n * CHW + (size_t)cs * (CHW / 8);
        const float4* src = (const float4*)(grdf + base);
        unsigned* dst = (unsigned*)(d_grd8 + base);
        float s = 0.f;
#pragma unroll 4
        for (int i = t; i < CHW / 8 / 4; i += 1024) {
            float4 v = src[i];
            s = fmaf(v.x, v.x, s); s = fmaf(v.y, v.y, s);
            s = fmaf(v.z, v.z, s); s = fmaf(v.w, v.w, s);
            unsigned o = (unsigned)f2e4m3(v.x) | ((unsigned)f2e4m3(v.y) << 8)
                       | ((unsigned)f2e4m3(v.z) << 16) | ((unsigned)f2e4m3(v.w) << 24);
            dst[i] = o;
        }
        __shared__ float r[32];
        for (int o = 16; o > 0; o >>= 1) s += __shfl_down_sync(0xffffffffu, s, o);
        int lane = t & 31, wid = t >> 5;
        if (lane == 0) r[wid] = s;
        __syncthreads();
        if (wid == 0) {
            s = (lane < 32) ? r[lane] : 0.f;
            for (int o = 16; o > 0; o >>= 1) s += __shfl_down_sync(0xffffffffu, s, o);
            if (lane == 0) d_gsqp[n][cs] = s;
        }
    }
}

// ---------------------------------------------------------------------------
// Window sums: sum 16 energy partials, then separable window sums -> d_part.
__global__ __launch_bounds__(1024)
void k_part2() {
    int m = blockIdx.x;
    int t = threadIdx.x;
    __shared__ float e[PLANE];
    __shared__ float cw[NS * NH];
    float4 s; s.x = s.y = s.z = s.w = 0.f;
#pragma unroll
    for (int cg = 0; cg < 16; cg++) {
        float4 v = ((const float4*)d_epart)[(m * 16 + cg) * 1024 + t];
        s.x += v.x; s.y += v.y; s.z += v.z; s.w += v.w;
    }
    ((float4*)e)[t] = s;
    __syncthreads();
    for (int k = t; k < NS * NH; k += 1024) {
        int j = k / NH, h = k % NH;
        int lo = j - 8; if (lo < 0) lo = 0;
        int hi = j - 8 + 64; if (hi > NW) hi = NW;
        float v = 0.f;
        for (int w = lo; w < hi; w++) v += e[h * NW + w];
        cw[j * NH + h] = v;
    }
    __syncthreads();
    for (int k = t; k < NPOS; k += 1024) {
        int i = k / NS, j = k % NS;
        int lo = i - 8; if (lo < 0) lo = 0;
        int hi = i - 8 + 64; if (hi > NH) hi = NH;
        float v = 0.f;
        for (int h = lo; h < hi; h++) v += cw[j * NH + h];
        d_part[m * NPOS + k] = v;
    }
}

// ---------------------------------------------------------------------------
__device__ __forceinline__ void mma16832_e4m3(float* c,
    unsigned a0, unsigned a1, unsigned a2, unsigned a3,
    unsigned b0, unsigned b1) {
    asm volatile(
        "mma.sync.aligned.m16n8k32.row.col.f32.e4m3.e4m3.f32 "
        "{%0,%1,%2,%3}, {%4,%5,%6,%7}, {%8,%9}, {%0,%1,%2,%3};"
        : "+f"(c[0]), "+f"(c[1]), "+f"(c[2]), "+f"(c[3])
        : "r"(a0), "r"(a1), "r"(a2), "r"(a3), "r"(b0), "r"(b1));
}

__device__ __forceinline__ void ldsm_x4(unsigned& a0, unsigned& a1,
                                        unsigned& a2, unsigned& a3,
                                        unsigned saddr) {
    asm volatile("ldmatrix.sync.aligned.m8n8.x4.shared.b16 {%0,%1,%2,%3}, [%4];"
        : "=r"(a0), "=r"(a1), "=r"(a2), "=r"(a3) : "r"(saddr));
}

__device__ __forceinline__ void cpasync16(unsigned dst, const void* src) {
    asm volatile("cp.async.ca.shared.global [%0], [%1], 16;" :: "r"(dst), "l"(src));
}
#define CP_COMMIT() asm volatile("cp.async.commit_group;")
#define CP_WAIT2()  asm volatile("cp.async.wait_group 2;")
#define CP_WAIT1()  asm volatile("cp.async.wait_group 1;")
#define CP_WAIT0()  asm volatile("cp.async.wait_group 0;")

// ---------------------------------------------------------------------------
// Main correlation on FP8 tensor cores (m16n8k32 e4m3, fp32 accum).
// Block = (m, k-split of [tbeg,tend) 4-row bands); 592 blocks = 4/SM.
// 128 threads = 4 warps. C[n=16, p=320] = sum_k grd[n,k]*satshift[k,p].
// B = computed-address 4B loads from FOUR shift-parity (dj mod 4) padded
// fp8 sat copies; A = grd via ldmatrix.x4 on 32B fp8 rows (one fetch per
// 10 mmas). grd bands in 3-stage cp.async ring; inner loop 2-stage pipelined.
__global__ __launch_bounds__(128, 4)
void k_corr_mma(const float* __restrict__ satf, const float* __restrict__ grdf) {
    __shared__ __align__(16) unsigned char sp[4 * SPN];       // 4 shift copies
    __shared__ __align__(16) unsigned char gsh[NSTAGE * BUFB];

    int m = blockIdx.x;
    int tbeg = (blockIdx.y * NBT) / CSPL;
    int tend = ((blockIdx.y + 1) * NBT) / CSPL;
    int t = threadIdx.x;
    int lane = t & 31, warp = t >> 5;
    int tig = lane & 3, grp = lane >> 2;

    // Zero all copies once (borders + spill rows stay zero forever).
    for (int i = t; i < 4 * SPN / 4; i += 128) ((unsigned*)sp)[i] = 0u;

    // Per-thread, per-tile B-fragment base byte offsets.
    int boff[NTILE];
#pragma unroll
    for (int tt = 0; tt < NTILE; tt++) {
        int p = warp * 80 + tt * 8 + grp;        // B-frag column = groupID
        int di = p / 17, dj = p % 17;            // p<=319 -> di<=18 (zero spill rows)
        boff[tt] = (dj & 3) * SPN + di * SW + (dj & ~3) + tig * 4;
    }

    // ldmatrix A lane roles: rows n, 16B column halves.
    unsigned gshb = (unsigned)__cvta_generic_to_shared(gsh);
    int arow = (lane & 7) + ((lane >> 3) & 1) * 8;
    unsigned aoff = (unsigned)(arow * GSB + ((lane & 16) ? 16 : 0));

    float acc[NTILE][4];
#pragma unroll
    for (int tt = 0; tt < NTILE; tt++)
#pragma unroll
        for (int k = 0; k < 4; k++) acc[tt][k] = 0.f;

    // ---- cp.async copy of one grd band (16 n x 256 fp8) into ring buf ----
    auto issue_copy = [&](int tb, int buf) {
        int c = tb >> 4, bb = tb & 15;
#pragma unroll
        for (int i = 0; i < 2; i++) {
            int q = t + i * 128;
            int n = q >> 4, ch = q & 15;
            const unsigned char* src =
                d_grd8 + ((size_t)(n * NC + c) * PLANE) + (bb << 8) + (ch << 4);
            unsigned dst = gshb + (unsigned)(buf * BUFB + n * GSB + (ch << 4));
            cpasync16(dst, src);
        }
    };

    issue_copy(tbeg, 0);
    CP_COMMIT();
    if (tbeg + 1 < tend) { issue_copy(tbeg + 1, 1); CP_COMMIT(); }
    int cbuf = 0, ibuf = 2;

    for (int tb = tbeg; tb < tend; tb++) {
        __syncthreads();   // all warps done with band tb-1 compute / sp reads
        if (tb + 2 < tend) {
            issue_copy(tb + 2, ibuf); CP_COMMIT();
            ibuf = (ibuf == NSTAGE-1) ? 0 : ibuf + 1;
        }
        if (tb == tbeg || (tb & 15) == 0) {
            // Build 4 shift copies of channel tb>>4's fp8 plane.
            // copy_c[x] = padded[x+c]; word store via funnelshift of source words.
            const unsigned* srow = (const unsigned*)(d_sat8 + (size_t)(m*NC + (tb >> 4)) * PLANE);
            for (int idx = t; idx < 64 * 68; idx += 128) {
                int row = idx / 68, rem = idx % 68;
                int j = 1 + (rem >> 2), c = rem & 3;
                unsigned lo = (j >= 2 && j < 18) ? srow[row * 16 + j - 2] : 0u;
                unsigned hi = (j < 17) ? srow[row * 16 + j - 1] : 0u;
                unsigned v = __funnelshift_r(lo, hi, c * 8);
                *(unsigned*)&sp[c * SPN + (row + 8) * SW + 4 * j] = v;
            }
        }
        int rem = tend - 1 - tb;
        if (rem >= 2) CP_WAIT2(); else if (rem == 1) CP_WAIT1(); else CP_WAIT0();
        __syncthreads();   // band tb data + sp visible to all

        // ---- compute band tb: 8 pipelined steps of 10 k32 mmas ----
        int hb = (tb & 15) << 2;
        int bofft[NTILE];
#pragma unroll
        for (int tt = 0; tt < NTILE; tt++) bofft[tt] = boff[tt] + hb * SW;
        unsigned abb = gshb + (unsigned)(cbuf * BUFB) + aoff;
        cbuf = (cbuf == NSTAGE-1) ? 0 : cbuf + 1;

        unsigned A0[4], B0[2*NTILE], A1[4], B1[2*NTILE];
        // step s: hh = s>>1 (band row), w0 = (s&1)*32; A k-bytes = s*32.
        {
            ldsm_x4(A0[0],A0[1],A0[2],A0[3], abb);
#pragma unroll
            for (int tt = 0; tt < NTILE; tt++) {
                const unsigned char* bp = sp + bofft[tt];
                B0[2*tt]   = *(const unsigned*)bp;
                B0[2*tt+1] = *(const unsigned*)(bp + 16);
            }
        }
#pragma unroll
        for (int u = 0; u < 4; u++) {
            {   // load step 2u+1
                int s = 2*u + 1;
                ldsm_x4(A1[0],A1[1],A1[2],A1[3], abb + (unsigned)(s * 32));
                int off = (s >> 1) * SW + (s & 1) * 32;
#pragma unroll
                for (int tt = 0; tt < NTILE; tt++) {
                    const unsigned char* bp = sp + bofft[tt] + off;
                    B1[2*tt]   = *(const unsigned*)bp;
                    B1[2*tt+1] = *(const unsigned*)(bp + 16);
                }
            }
#pragma unroll
            for (int tt = 0; tt < NTILE; tt++)
                mma16832_e4m3(acc[tt], A0[0],A0[1],A0[2],A0[3], B0[2*tt], B0[2*tt+1]);
            {   // load step (2u+2)&7 (wraps to 0 on last pair: harmless reload)
                int s = (2*u + 2) & 7;
                ldsm_x4(A0[0],A0[1],A0[2],A0[3], abb + (unsigned)(s * 32));
                int off = (s >> 1) * SW + (s & 1) * 32;
#pragma unroll
                for (int tt = 0; tt < NTILE; tt++) {
                    const unsigned char* bp = sp + bofft[tt] + off;
                    B0[2*tt]   = *(const unsigned*)bp;
                    B0[2*tt+1] = *(const unsigned*)(bp + 16);
                }
            }
#pragma unroll
            for (int tt = 0; tt < NTILE; tt++)
                mma16832_e4m3(acc[tt], A1[0],A1[1],A1[2],A1[3], B1[2*tt], B1[2*tt+1]);
        }
    }

    // C layout: c0=C[grp][tig*2], c1=[grp][tig*2+1], c2=[grp+8][tig*2], c3=[grp+8][tig*2+1]
#pragma unroll
    for (int tt = 0; tt < NTILE; tt++) {
        int p0 = warp * 80 + tt * 8 + tig * 2;
        if (p0 < NPOS) {
            atomicAdd(&d_dot[(m * 16 + grp) * NPOS + p0],     acc[tt][0]);
            atomicAdd(&d_dot[(m * 16 + grp + 8) * NPOS + p0], acc[tt][2]);
            if (p0 + 1 < NPOS) {
                atomicAdd(&d_dot[(m * 16 + grp) * NPOS + p0 + 1],     acc[tt][1]);
                atomicAdd(&d_dot[(m * 16 + grp + 8) * NPOS + p0 + 1], acc[tt][3]);
            }
        }
    }
    (void)satf; (void)grdf;
}

// ---------------------------------------------------------------------------
__device__ __forceinline__ float softplusf(float x) {
    return fmaxf(x, 0.f) + log1pf(expf(-fabsf(x)));
}

// Per-pair max-similarity -> dist. grid 8 x 1024: warp per (m,n) pair.
__global__ __launch_bounds__(1024)
void k_sim() {
    int pair = blockIdx.x * 32 + (threadIdx.x >> 5);   // 0..255
    int lane = threadIdx.x & 31;
    int m = pair >> 4, n = pair & 15;
    const float* dp = d_dot + pair * NPOS;
    const float* pp = d_part + m * NPOS;
    float best = -3.4e38f;
    for (int k = lane; k < NPOS; k += 32)
        best = fmaxf(best, dp[k] * rsqrtf(pp[k]));
    for (int o = 16; o > 0; o >>= 1)
        best = fmaxf(best, __shfl_xor_sync(0xffffffffu, best, o));
    if (lane == 0) {
        float g = 0.f;
        for (int j = 0; j < 8; j++) g += d_gsqp[n][j];
        d_dist[pair] = 2.f - 2.f * best / sqrtf(g);
    }
}

// Final loss from dist matrix. One block of 256.
__global__ void k_final2(float* __restrict__ out) {
    __shared__ float pos[NB];
    __shared__ float red[256];
    __shared__ float rowmin[NB];
    int t = threadIdx.x;
    float dv = d_dist[t];
    int m = t >> 4, n = t & 15;
    if (m == n) pos[m] = dv;
    __syncthreads();
    red[t] = softplusf((pos[n] - dv) * 10.f) + softplusf((pos[m] - dv) * 10.f);
    if (t < NB) {
        float mn = 3.4e38f;
        for (int k = 0; k < NB; k++) mn = fminf(mn, d_dist[t * NB + k]);
        rowmin[t] = mn;
    }
    __syncthreads();
    for (int s = 128; s > 0; s >>= 1) {
        if (t < s) red[t] += red[t + s];
        __syncthreads();
    }
    if (t == 0) {
        float pair_n = (float)(NB * (NB - 1));
        float loss = 10.f * (red[0] / (2.f * pair_n));
        float ps = 0.f, ms = 0.f;
        for (int k = 0; k < NB; k++) { ps += pos[k]; ms += rowmin[k]; }
        out[0] = loss;
        out[1] = ps / NB;
        out[2] = ms / NB;
    }
}

// ---------------------------------------------------------------------------
extern "C" void kernel_launch(void* const* d_in, const int* in_sizes, int n_in,
                              void* d_out, int out_size) {
    const float* sat = (const float*)d_in[0];
    const float* grd = (const float*)d_in[1];
    float* out = (float*)d_out;

    k_prep<<<dim3(NB, 24), 1024>>>(sat, grd);      // fp8 convert + partials + zero
    k_corr_mma<<<dim3(NB, CSPL), 128>>>(sat, grd);
    k_part2<<<NB, 1024>>>();                        // window sums -> d_part
    k_sim<<<8, 1024>>>();                           // dist matrix
    k_final2<<<1, 256>>>(out);
}